// round 14
// baseline (speedup 1.0000x reference)
#include <cuda_runtime.h>
#include <math.h>
#include <stdint.h>

// ---------------- problem constants ----------------
#define Bc   32
#define NRc  4096
#define DIN  384
#define DCTX 128
#define Hc   64
#define Ac   16
#define MTOT (Bc * NRc)

#define LOG_VAR2_C  (-4.6051701859880914f)
#define INV_VAR2_C  (100.0f)
#define STD2_C      (0.1f)

// ---------------- device scratch (zero-init at module load; scan re-zeros
// g_mse/g_kld at end of every launch so each launch starts from zeros) ----------
__device__ float g_embT[(size_t)Bc * Hc * NRc];   // [b][k][n]
__device__ float g_mse[Bc];
__device__ float g_kld[Bc];

// ---------------- tf32 helpers ----------------
__device__ __forceinline__ float tf32r(float x) {
    uint32_t u; asm("cvt.rna.tf32.f32 %0, %1;" : "=r"(u) : "f"(x));
    return __uint_as_float(u);
}
__device__ __forceinline__ void mma_tf32(float c[4], const uint32_t a[4],
                                         uint32_t b0, uint32_t b1) {
    asm volatile("mma.sync.aligned.m16n8k8.row.col.f32.tf32.tf32.f32 "
        "{%0,%1,%2,%3}, {%4,%5,%6,%7}, {%8,%9}, {%0,%1,%2,%3};"
        : "+f"(c[0]), "+f"(c[1]), "+f"(c[2]), "+f"(c[3])
        : "r"(a[0]), "r"(a[1]), "r"(a[2]), "r"(a[3]), "r"(b0), "r"(b1));
}

#define WSP 68   // conflict-free row stride (floats)

// ---------------- fused VAE kernel ----------------
// GEMM1 k-tile 32 (half the syncs); merged W22/W21 GEMM; l2norm fused via shfl.
// smem: As 32*128, Bs 32*64, Hs 128*65, Ws 64*WSP, Ws2 64*64, red 64, rns 128
#define VAE_SMEM_FLOATS (4096 + 2048 + 8320 + 64*WSP + 4096 + 64 + 128)

__global__ __launch_bounds__(256, 2)
void vae_kernel(const float* __restrict__ roles, const float* __restrict__ eps,
                const float* __restrict__ W1,  const float* __restrict__ b1,
                const float* __restrict__ W21, const float* __restrict__ b21,
                const float* __restrict__ W22, const float* __restrict__ b22,
                const float* __restrict__ W3,  const float* __restrict__ b3,
                const float* __restrict__ W4,  const float* __restrict__ b4)
{
    extern __shared__ float sm[];
    float* As  = sm;                 // 32*128
    float* Bs  = As + 4096;          // 32*64
    float* Hs  = Bs + 2048;          // 128*65
    float* Ws  = Hs + 8320;          // 64*WSP  (W22 plain / W3,W4 permuted)
    float* Ws2 = Ws + 64*WSP;        // 64*64   (W21 plain)
    float* red = Ws2 + 4096;         // 64
    float* rns = red + 64;           // 128

    const int tid  = threadIdx.x;
    const int tcol = tid & 15;
    const int trow = tid >> 4;
    const int row0 = blockIdx.x * 128;
    const int b    = row0 >> 12;

    float acc[8][4];

    // ================= GEMM1: h = relu(roles @ W1 + b1)  [fp32, k-tile 32] ======
#pragma unroll
    for (int i = 0; i < 8; i++)
#pragma unroll
        for (int j = 0; j < 4; j++) acc[i][j] = 0.0f;

    // A staging: 4 slots/thread, f = tid + q*256 in [0,1024): m=f>>3, k4=(f&7)*4
    // B staging: 2 slots/thread, f = tid + q*256 in [0,512):  k=f>>4, j4=(f&15)*4
    int amq[4], akq[4];
#pragma unroll
    for (int q = 0; q < 4; q++) { int f = tid + q*256; amq[q] = f >> 3; akq[q] = (f & 7) * 4; }
    const int bk0 = tid >> 4;                 // 0..15
    const int bk1 = (tid + 256) >> 4;         // 16..31
    const int bj4 = (tid & 15) * 4;

    float4 va[4], vb0, vb1;
#pragma unroll
    for (int q = 0; q < 4; q++)
        va[q] = *reinterpret_cast<const float4*>(roles + (size_t)(row0 + amq[q]) * DIN + akq[q]);
    vb0 = *reinterpret_cast<const float4*>(W1 + (size_t)bk0 * Hc + bj4);
    vb1 = *reinterpret_cast<const float4*>(W1 + (size_t)bk1 * Hc + bj4);

    for (int t = 0; t < 12; t++) {
#pragma unroll
        for (int q = 0; q < 4; q++) {
            As[(akq[q] + 0) * 128 + amq[q]] = va[q].x;
            As[(akq[q] + 1) * 128 + amq[q]] = va[q].y;
            As[(akq[q] + 2) * 128 + amq[q]] = va[q].z;
            As[(akq[q] + 3) * 128 + amq[q]] = va[q].w;
        }
        *reinterpret_cast<float4*>(&Bs[bk0 * 64 + bj4]) = vb0;
        *reinterpret_cast<float4*>(&Bs[bk1 * 64 + bj4]) = vb1;
        __syncthreads();

        if (t + 1 < 12) {
            const int kt = (t + 1) * 32;
#pragma unroll
            for (int q = 0; q < 4; q++)
                va[q] = *reinterpret_cast<const float4*>(
                    roles + (size_t)(row0 + amq[q]) * DIN + kt + akq[q]);
            vb0 = *reinterpret_cast<const float4*>(W1 + (size_t)(kt + bk0) * Hc + bj4);
            vb1 = *reinterpret_cast<const float4*>(W1 + (size_t)(kt + bk1) * Hc + bj4);
        }

#pragma unroll
        for (int k = 0; k < 32; k++) {
            float a[8];
            *reinterpret_cast<float4*>(&a[0]) = *reinterpret_cast<float4*>(&As[k*128 + trow*8]);
            *reinterpret_cast<float4*>(&a[4]) = *reinterpret_cast<float4*>(&As[k*128 + trow*8 + 4]);
            float4 bb = *reinterpret_cast<float4*>(&Bs[k*64 + tcol*4]);
#pragma unroll
            for (int i = 0; i < 8; i++) {
                acc[i][0] += a[i] * bb.x;
                acc[i][1] += a[i] * bb.y;
                acc[i][2] += a[i] * bb.z;
                acc[i][3] += a[i] * bb.w;
            }
        }
        __syncthreads();
    }
    {
        float4 bv = *reinterpret_cast<const float4*>(b1 + tcol * 4);
#pragma unroll
        for (int i = 0; i < 8; i++) {
            int r = trow * 8 + i;
            Hs[r*65 + tcol*4 + 0] = fmaxf(acc[i][0] + bv.x, 0.0f);
            Hs[r*65 + tcol*4 + 1] = fmaxf(acc[i][1] + bv.y, 0.0f);
            Hs[r*65 + tcol*4 + 2] = fmaxf(acc[i][2] + bv.z, 0.0f);
            Hs[r*65 + tcol*4 + 3] = fmaxf(acc[i][3] + bv.w, 0.0f);
        }
    }
    // stage BOTH W22 (Ws, plain) and W21 (Ws2, plain)
    for (int t = tid; t < 1024; t += 256) {
        *reinterpret_cast<float4*>(&Ws [t*4]) = *reinterpret_cast<const float4*>(W22 + t*4);
        *reinterpret_cast<float4*>(&Ws2[t*4]) = *reinterpret_cast<const float4*>(W21 + t*4);
    }
    __syncthreads();

    float kacc = 0.0f;

    // ========== MERGED: log_var = h@W22+b22  AND  mu = h@W21+b21  [fp32] ========
    float ac2[8][4];
#pragma unroll
    for (int i = 0; i < 8; i++)
#pragma unroll
        for (int j = 0; j < 4; j++) { acc[i][j] = 0.0f; ac2[i][j] = 0.0f; }
#pragma unroll 4
    for (int k = 0; k < 64; k++) {
        float a[8];
#pragma unroll
        for (int i = 0; i < 8; i++) a[i] = Hs[(trow*8 + i)*65 + k];
        float4 b2 = *reinterpret_cast<float4*>(&Ws [k*64 + tcol*4]);
        float4 b1v = *reinterpret_cast<float4*>(&Ws2[k*64 + tcol*4]);
#pragma unroll
        for (int i = 0; i < 8; i++) {
            ac2[i][0] += a[i]*b2.x;  ac2[i][1] += a[i]*b2.y;
            ac2[i][2] += a[i]*b2.z;  ac2[i][3] += a[i]*b2.w;
            acc[i][0] += a[i]*b1v.x; acc[i][1] += a[i]*b1v.y;
            acc[i][2] += a[i]*b1v.z; acc[i][3] += a[i]*b1v.w;
        }
    }
    // fused epilogue: kld terms + z = mu + eps * exp(0.5 lv) * STD2
    {
        float4 bv22 = *reinterpret_cast<const float4*>(b22 + tcol * 4);
        float4 bv21 = *reinterpret_cast<const float4*>(b21 + tcol * 4);
        float b22a[4] = {bv22.x, bv22.y, bv22.z, bv22.w};
        float b21a[4] = {bv21.x, bv21.y, bv21.z, bv21.w};
#pragma unroll
        for (int i = 0; i < 8; i++) {
            float4 ev = *reinterpret_cast<const float4*>(
                eps + (size_t)(row0 + trow*8 + i) * Hc + tcol * 4);
            float eva[4] = {ev.x, ev.y, ev.z, ev.w};
#pragma unroll
            for (int j = 0; j < 4; j++) {
                float lv = ac2[i][j] + b22a[j];
                float ex = expf(lv);
                kacc += (1.0f - LOG_VAR2_C + lv - ex * INV_VAR2_C);
                float mu = acc[i][j] + b21a[j];
                kacc -= mu * mu * INV_VAR2_C;
                float s  = expf(0.5f * lv) * STD2_C;
                acc[i][j] = mu + eva[j] * s;    // z
            }
        }
    }
    // ---- fused l2norm: row sums from z accumulators via 16-lane (tcol) shuffles
    float rn8[8];
#pragma unroll
    for (int i = 0; i < 8; i++) {
        float ss = acc[i][0]*acc[i][0] + acc[i][1]*acc[i][1]
                 + acc[i][2]*acc[i][2] + acc[i][3]*acc[i][3];
#pragma unroll
        for (int off = 1; off < 16; off <<= 1)
            ss += __shfl_xor_sync(0xffffffffu, ss, off);
        rn8[i] = 1.0f / fmaxf(sqrtf(ss), 1e-12f);
    }
    __syncthreads();           // merged-GEMM reads of Hs(h)/Ws/Ws2 complete
    // z (fp32) -> Hs ; rns -> smem ; stage Ws = permuted tf32(W3)
#pragma unroll
    for (int i = 0; i < 8; i++) {
        int r = trow * 8 + i;
        Hs[r*65 + tcol*4 + 0] = acc[i][0];
        Hs[r*65 + tcol*4 + 1] = acc[i][1];
        Hs[r*65 + tcol*4 + 2] = acc[i][2];
        Hs[r*65 + tcol*4 + 3] = acc[i][3];
    }
    if (tcol == 0) {
#pragma unroll
        for (int i = 0; i < 8; i++) rns[trow*8 + i] = rn8[i];
    }
    for (int t = tid; t < 4096; t += 256) {
        int k = t >> 6, n = t & 63;
        Ws[k*WSP + ((n & 7) << 3) + (n >> 3)] = tf32r(W3[t]);
    }
    __syncthreads();

    // ================= role_emb store (transposed) =================
    {
        const int nloc0 = row0 & (NRc - 1);
        for (int t = tid; t < 128 * 64; t += 256) {
            int k = t >> 7;
            int r = t & 127;
            g_embT[((size_t)b * Hc + k) * NRc + nloc0 + r] = Hs[r*65 + k] * rns[r];
        }
    }

    // ================= tf32 HMMA path: g = relu(z@W3+b3); mse(g@W4+b4) ========
    const int wid  = tid >> 5;
    const int lane = tid & 31;
    const int gid  = lane >> 2;
    const int tig  = lane & 3;
    const int mrow = wid * 16;

    uint32_t afr[8][4];
#pragma unroll
    for (int kt = 0; kt < 8; kt++) {
        int k0 = kt * 8;
        afr[kt][0] = __float_as_uint(tf32r(Hs[(mrow+gid  )*65 + k0+tig  ]));
        afr[kt][1] = __float_as_uint(tf32r(Hs[(mrow+gid+8)*65 + k0+tig  ]));
        afr[kt][2] = __float_as_uint(tf32r(Hs[(mrow+gid  )*65 + k0+tig+4]));
        afr[kt][3] = __float_as_uint(tf32r(Hs[(mrow+gid+8)*65 + k0+tig+4]));
    }
    float cfr[8][4];
#pragma unroll
    for (int nt = 0; nt < 8; nt++)
#pragma unroll
        for (int j = 0; j < 4; j++) cfr[nt][j] = 0.0f;
#pragma unroll
    for (int kt = 0; kt < 8; kt++) {
        const float4* p0 = reinterpret_cast<const float4*>(&Ws[(kt*8+tig  )*WSP + gid*8]);
        const float4* p1 = reinterpret_cast<const float4*>(&Ws[(kt*8+tig+4)*WSP + gid*8]);
        float4 b0a = p0[0], b0b = p0[1];
        float4 b1a = p1[0], b1b = p1[1];
        mma_tf32(cfr[0], afr[kt], __float_as_uint(b0a.x), __float_as_uint(b1a.x));
        mma_tf32(cfr[1], afr[kt], __float_as_uint(b0a.y), __float_as_uint(b1a.y));
        mma_tf32(cfr[2], afr[kt], __float_as_uint(b0a.z), __float_as_uint(b1a.z));
        mma_tf32(cfr[3], afr[kt], __float_as_uint(b0a.w), __float_as_uint(b1a.w));
        mma_tf32(cfr[4], afr[kt], __float_as_uint(b0b.x), __float_as_uint(b1b.x));
        mma_tf32(cfr[5], afr[kt], __float_as_uint(b0b.y), __float_as_uint(b1b.y));
        mma_tf32(cfr[6], afr[kt], __float_as_uint(b0b.z), __float_as_uint(b1b.z));
        mma_tf32(cfr[7], afr[kt], __float_as_uint(b0b.w), __float_as_uint(b1b.w));
    }
    __syncthreads();
#pragma unroll
    for (int nt = 0; nt < 8; nt++) {
        int col = nt*8 + 2*tig;
        float2 b3v = *reinterpret_cast<const float2*>(b3 + col);
        Hs[(mrow+gid  )*65 + col    ] = tf32r(fmaxf(cfr[nt][0] + b3v.x, 0.0f));
        Hs[(mrow+gid  )*65 + col + 1] = tf32r(fmaxf(cfr[nt][1] + b3v.y, 0.0f));
        Hs[(mrow+gid+8)*65 + col    ] = tf32r(fmaxf(cfr[nt][2] + b3v.x, 0.0f));
        Hs[(mrow+gid+8)*65 + col + 1] = tf32r(fmaxf(cfr[nt][3] + b3v.y, 0.0f));
    }
    __syncthreads();
#pragma unroll
    for (int kt = 0; kt < 8; kt++) {
        int k0 = kt * 8;
        afr[kt][0] = __float_as_uint(Hs[(mrow+gid  )*65 + k0+tig  ]);
        afr[kt][1] = __float_as_uint(Hs[(mrow+gid+8)*65 + k0+tig  ]);
        afr[kt][2] = __float_as_uint(Hs[(mrow+gid  )*65 + k0+tig+4]);
        afr[kt][3] = __float_as_uint(Hs[(mrow+gid+8)*65 + k0+tig+4]);
    }

    // W4 chunk staging: thread owns 16 consecutive floats; double-buffered
    const int sk = tid >> 2;
    const int sn = (tid & 3) * 16;
    float4 wpre[4];
#pragma unroll
    for (int q = 0; q < 4; q++)
        wpre[q] = *reinterpret_cast<const float4*>(
            W4 + (size_t)sk * DIN + sn + q * 4);

    float msacc = 0.0f;
    for (int ch = 0; ch < 6; ch++) {
        __syncthreads();
        {
            const float* wf = reinterpret_cast<const float*>(wpre);
#pragma unroll
            for (int j = 0; j < 16; j++) {
                int n = sn + j;
                Ws[sk*WSP + ((n & 7) << 3) + (n >> 3)] = tf32r(wf[j]);
            }
        }
        __syncthreads();
        if (ch + 1 < 6) {
#pragma unroll
            for (int q = 0; q < 4; q++)
                wpre[q] = *reinterpret_cast<const float4*>(
                    W4 + (size_t)sk * DIN + (ch + 1) * 64 + sn + q * 4);
        }
        float cf[8][4];
#pragma unroll
        for (int nt = 0; nt < 8; nt++)
#pragma unroll
            for (int j = 0; j < 4; j++) cf[nt][j] = 0.0f;
#pragma unroll
        for (int kt = 0; kt < 8; kt++) {
            const float4* p0 = reinterpret_cast<const float4*>(&Ws[(kt*8+tig  )*WSP + gid*8]);
            const float4* p1 = reinterpret_cast<const float4*>(&Ws[(kt*8+tig+4)*WSP + gid*8]);
            float4 b0a = p0[0], b0b = p0[1];
            float4 b1a = p1[0], b1b = p1[1];
            mma_tf32(cf[0], afr[kt], __float_as_uint(b0a.x), __float_as_uint(b1a.x));
            mma_tf32(cf[1], afr[kt], __float_as_uint(b0a.y), __float_as_uint(b1a.y));
            mma_tf32(cf[2], afr[kt], __float_as_uint(b0a.z), __float_as_uint(b1a.z));
            mma_tf32(cf[3], afr[kt], __float_as_uint(b0a.w), __float_as_uint(b1a.w));
            mma_tf32(cf[4], afr[kt], __float_as_uint(b0b.x), __float_as_uint(b1b.x));
            mma_tf32(cf[5], afr[kt], __float_as_uint(b0b.y), __float_as_uint(b1b.y));
            mma_tf32(cf[6], afr[kt], __float_as_uint(b0b.z), __float_as_uint(b1b.z));
            mma_tf32(cf[7], afr[kt], __float_as_uint(b0b.w), __float_as_uint(b1b.w));
        }
#pragma unroll
        for (int nt = 0; nt < 8; nt++) {
            int col = ch*64 + nt*8 + 2*tig;
            float2 b4v = *reinterpret_cast<const float2*>(b4 + col);
            float2 r0v = *reinterpret_cast<const float2*>(
                roles + (size_t)(row0 + mrow + gid    ) * DIN + col);
            float2 r1v = *reinterpret_cast<const float2*>(
                roles + (size_t)(row0 + mrow + gid + 8) * DIN + col);
            float d;
            d = cf[nt][0] + b4v.x - r0v.x; msacc += d*d;
            d = cf[nt][1] + b4v.y - r0v.y; msacc += d*d;
            d = cf[nt][2] + b4v.x - r1v.x; msacc += d*d;
            d = cf[nt][3] + b4v.y - r1v.y; msacc += d*d;
        }
    }

    // ================= block reduce kld / mse =================
    float ks = kacc, ms = msacc;
#pragma unroll
    for (int off = 16; off > 0; off >>= 1) {
        ks += __shfl_xor_sync(0xffffffffu, ks, off);
        ms += __shfl_xor_sync(0xffffffffu, ms, off);
    }
    __syncthreads();
    if ((tid & 31) == 0) { red[tid >> 5] = ks; red[8 + (tid >> 5)] = ms; }
    __syncthreads();
    if (tid == 0) {
        float kt = 0.0f, mt = 0.0f;
#pragma unroll
        for (int w = 0; w < 8; w++) { kt += red[w]; mt += red[8 + w]; }
        atomicAdd(&g_kld[b], kt);
        atomicAdd(&g_mse[b], mt);
    }
}

// ---------------- cluster / mbarrier helpers ----------------
__device__ __forceinline__ uint32_t s2u(const void* p) {
    uint32_t a;
    asm("{ .reg .u64 t; cvta.to.shared.u64 t, %1; cvt.u32.u64 %0, t; }" : "=r"(a) : "l"(p));
    return a;
}
__device__ __forceinline__ void mbar_init(uint32_t mbar, uint32_t cnt) {
    asm volatile("mbarrier.init.shared.b64 [%0], %1;" :: "r"(mbar), "r"(cnt) : "memory");
}
__device__ __forceinline__ void mbar_expect_tx(uint32_t mbar, uint32_t bytes) {
    asm volatile("mbarrier.arrive.expect_tx.shared.b64 _, [%0], %1;"
                 :: "r"(mbar), "r"(bytes) : "memory");
}
__device__ __forceinline__ void st_async_b32(uint32_t slot, uint32_t mbar,
                                             uint32_t peer, uint32_t val) {
    uint32_t rs, rb;
    asm("mapa.shared::cluster.u32 %0, %1, %2;" : "=r"(rs) : "r"(slot), "r"(peer));
    asm("mapa.shared::cluster.u32 %0, %1, %2;" : "=r"(rb) : "r"(mbar), "r"(peer));
    asm volatile("st.async.shared::cluster.mbarrier::complete_tx::bytes.b32 [%0], %1, [%2];"
                 :: "r"(rs), "r"(val), "r"(rb) : "memory");
}
__device__ __forceinline__ void mbar_wait_cluster(uint32_t mbar, uint32_t parity) {
    uint32_t done;
    asm volatile("{\n\t.reg .pred p;\n\t"
        "mbarrier.try_wait.parity.acquire.cluster.shared::cta.b64 p, [%1], %2;\n\t"
        "selp.b32 %0, 1, 0, p;\n\t}"
        : "=r"(done) : "r"(mbar), "r"(parity) : "memory");
    while (!done) {
        asm volatile("{\n\t.reg .pred p;\n\t"
            "mbarrier.try_wait.parity.acquire.cluster.shared::cta.b64 p, [%1], %2, 0x989680;\n\t"
            "selp.b32 %0, 1, 0, p;\n\t}"
            : "=r"(done) : "r"(mbar), "r"(parity) : "memory");
    }
}
#define CLUSTER_SYNC() do { \
    asm volatile("barrier.cluster.arrive.aligned;" ::: "memory"); \
    asm volatile("barrier.cluster.wait.aligned;"   ::: "memory"); } while (0)

// ---------------- cluster-parallel selection scan (frozen) ----------
#define CL 4
#define STH 512
#define RPC (NRc / CL)
#define NCACHE 768
#define SCAN_SMEM_FLOATS (1024 + 64*NCACHE)

__global__ __launch_bounds__(STH, 1) __cluster_dims__(CL, 1, 1)
void scan_kernel(const float* __restrict__ contexts, const float* __restrict__ rand_vals,
                 const float* __restrict__ Wc, const float* __restrict__ bc,
                 const float* __restrict__ init_emb, float* __restrict__ out)
{
    extern __shared__ float sm[];
    unsigned long long* mbar = (unsigned long long*)sm;
    float* exchS = sm + 4;
    int*   exchC = (int*)(sm + 12);
    int*   seli  = (int*)(sm + 20);
    float* scal  = sm + 21;
    float* wred  = sm + 28;
    float* wexc  = sm + 44;
    float* ctxs  = sm + 60;
    float* bcs   = sm + 188;
    float* hist  = sm + 252;
    float* cur   = sm + 316;
    float* tmp   = sm + 380;
    float* cvec  = sm + 444;
    float* cpart = sm + 508;
    float* embc  = sm + 1024;

    const int b    = blockIdx.x >> 2;
    const int rank = blockIdx.x & 3;
    const int tid  = threadIdx.x;
    const int lane = tid & 31;
    const int wid  = tid >> 5;

    if (blockIdx.x == 0 && tid == 0) {
        float v = 0.0f;
        for (int bb = 0; bb < Bc; bb++) {
            float mse = g_mse[bb] * (1.0f / ((float)NRc * (float)DIN));
            float kld = (-0.5f / ((float)NRc * (float)Hc)) * g_kld[bb];
            v += mse + kld;
        }
        out[Bc*Ac + Bc + Bc*Hc] = v / (float)Bc;
        for (int bb = 0; bb < Bc; bb++) { g_mse[bb] = 0.0f; g_kld[bb] = 0.0f; }
    }

    const uint32_t mbarS_a = s2u(&mbar[0]);
    const uint32_t mbarC_a = s2u(&mbar[1]);

    const float* embT = g_embT + (size_t)b * Hc * NRc;

    const int col  = tid & 63;
    const int irow = (tid >> 6) * 24;
    float wreg[24];
#pragma unroll
    for (int i = 0; i < 24; i++) wreg[i] = Wc[(size_t)(irow + i) * 64 + col];

    for (int t = tid; t < 64 * NCACHE / 4; t += STH) {
        int k  = t / (NCACHE / 4);
        int n4 = (t % (NCACHE / 4)) * 4;
        *reinterpret_cast<float4*>(&embc[k * NCACHE + n4]) =
            *reinterpret_cast<const float4*>(embT + (size_t)k * NRc + rank * RPC + n4);
    }
    if (tid < 128) ctxs[tid] = contexts[b * DCTX + tid];
    if (tid < 64)  { bcs[tid] = bc[tid]; float iv = init_emb[tid]; hist[tid] = iv; cur[tid] = iv; }
    if (tid == 0)  {
        scal[0] = 0.0f;
        mbar_init(mbarS_a, 1);
        mbar_init(mbarC_a, 1);
    }
    __syncthreads();
    CLUSTER_SYNC();

    for (int step = 0; step < Ac; step++) {
        const uint32_t par = (uint32_t)(step & 1);
        const uint32_t slotS = s2u(&exchS[(step & 1) * 4 + rank]);
        const uint32_t slotC = s2u(&exchC[(step & 1) * 4 + rank]);

        if (tid == 0) {
            mbar_expect_tx(mbarS_a, 16);
            mbar_expect_tx(mbarC_a, 16);
            seli[0] = 0x7fffffff;
        }
        if (tid < 64) tmp[tid] = hist[tid] + cur[tid];
        __syncthreads();
        if (wid == 0) {
            float x0 = tmp[lane], x1 = tmp[lane + 32];
            float s = x0 + x1;
#pragma unroll
            for (int off = 16; off > 0; off >>= 1) s += __shfl_xor_sync(0xffffffffu, s, off);
            float mean = s * (1.0f / 64.0f);
            float d0 = x0 - mean, d1 = x1 - mean;
            float vs = d0*d0 + d1*d1;
#pragma unroll
            for (int off = 16; off > 0; off >>= 1) vs += __shfl_xor_sync(0xffffffffu, vs, off);
            if (lane == 0) {
                scal[1] = mean;
                scal[2] = 1.0f / sqrtf(vs * (1.0f / 64.0f) + 1e-5f);
            }
        }
        __syncthreads();
        if (tid < 64) hist[tid] = (tmp[tid] - scal[1]) * scal[2];
        __syncthreads();

        {
            float s = 0.0f;
#pragma unroll
            for (int i = 0; i < 24; i++) {
                int gi = irow + i;
                float x = (gi < 128) ? ctxs[gi] : hist[gi - 128];
                s = fmaf(x, wreg[i], s);
            }
            cpart[(tid >> 6) * 64 + col] = s;
        }
        __syncthreads();
        if (tid < 64) {
            float s = bcs[tid];
#pragma unroll
            for (int p = 0; p < 8; p++) s += cpart[p*64 + tid];
            cvec[tid] = s;
        }
        __syncthreads();

        float invc;
        {
            float c0 = cvec[lane], c1 = cvec[lane + 32];
            float ssn = c0*c0 + c1*c1;
#pragma unroll
            for (int off = 16; off > 0; off >>= 1)
                ssn += __shfl_xor_sync(0xffffffffu, ssn, off);
            invc = 1.0f / fmaxf(sqrtf(ssn), 1e-12f);
        }

        float sx = 0.f, sy = 0.f;
        if (tid < NCACHE / 2) {
            const float* ep = embc + 2 * tid;
#pragma unroll 8
            for (int k = 0; k < 64; k++) {
                float2 v = *reinterpret_cast<const float2*>(ep + k * NCACHE);
                float ck = cvec[k];
                sx = fmaf(v.x, ck, sx); sy = fmaf(v.y, ck, sy);
            }
        } else {
            const float* ep = embT + rank * RPC + 2 * tid;
#pragma unroll 16
            for (int k = 0; k < 64; k++) {
                float2 v = *reinterpret_cast<const float2*>(ep + (size_t)k * NRc);
                float ck = cvec[k];
                sx = fmaf(v.x, ck, sx); sy = fmaf(v.y, ck, sy);
            }
        }
        float e0 = expf(sx * invc), e1 = expf(sy * invc);
        float t2 = e0 + e1;

        float incl = t2;
#pragma unroll
        for (int off = 1; off < 32; off <<= 1) {
            float n = __shfl_up_sync(0xffffffffu, incl, off);
            if (lane >= off) incl += n;
        }
        if (lane == 31) wred[wid] = incl;
        __syncthreads();
        if (tid == 0) {
            float s = 0.0f;
#pragma unroll
            for (int w = 0; w < 16; w++) { float v = wred[w]; wexc[w] = s; s += v; }
            scal[4] = s;
        }
        __syncthreads();
        float S_local  = scal[4];
        float excl_thr = wexc[wid] + (incl - t2);

        if (tid < CL) st_async_b32(slotS, mbarS_a, (uint32_t)tid, __float_as_uint(S_local));
        mbar_wait_cluster(mbarS_a, par);
        float S_tot = 0.0f, pre = 0.0f;
#pragma unroll
        for (int r = 0; r < CL; r++) {
            float v = exchS[(step & 1) * 4 + r];
            if (r < rank) pre += v;
            S_tot += v;
        }

        float T = rand_vals[b * Ac + step] * S_tot;
        float base = pre + excl_thr;
        int cand = 0x7fffffff;
        int gr = rank * RPC + tid * 2;
        if      (base + e0 > T) cand = gr;
        else if (base + t2 > T) cand = gr + 1;
        if (cand != 0x7fffffff) atomicMin(seli, cand);
        __syncthreads();
        int lc = seli[0];
        if (tid < CL) st_async_b32(slotC, mbarC_a, (uint32_t)tid, (uint32_t)lc);
        mbar_wait_cluster(mbarC_a, par);
        int sel = 0x7fffffff;
#pragma unroll
        for (int r = 0; r < CL; r++) sel = min(sel, exchC[(step & 1) * 4 + r]);
        if (sel == 0x7fffffff) sel = 0;

        if (tid < 64) cur[tid] = embT[(size_t)tid * NRc + sel];
        __syncthreads();
        if (wid == 0) {
            float d = cur[lane] * cvec[lane] + cur[lane + 32] * cvec[lane + 32];
#pragma unroll
            for (int off = 16; off > 0; off >>= 1) d += __shfl_xor_sync(0xffffffffu, d, off);
            if (lane == 0) scal[0] += d * invc - logf(S_tot);
        }
        if (rank == 0 && tid == 0) out[b * Ac + step] = (float)sel;
        __syncthreads();
    }

    if (rank == 0 && tid == 0) out[Bc*Ac + b] = scal[0];
    if (rank == 0 && tid < 64) out[Bc*Ac + Bc + b*Hc + tid] = hist[tid];
    CLUSTER_SYNC();
}

// ---------------- launcher ----------------
extern "C" void kernel_launch(void* const* d_in, const int* in_sizes, int n_in,
                              void* d_out, int out_size) {
    const float* roles     = (const float*)d_in[0];
    const float* contexts  = (const float*)d_in[1];
    const float* eps       = (const float*)d_in[2];
    const float* rand_vals = (const float*)d_in[3];
    const float* W1  = (const float*)d_in[5];
    const float* b1  = (const float*)d_in[6];
    const float* W21 = (const float*)d_in[7];
    const float* b21 = (const float*)d_in[8];
    const float* W22 = (const float*)d_in[9];
    const float* b22 = (const float*)d_in[10];
    const float* W3  = (const float*)d_in[11];
    const float* b3  = (const float*)d_in[12];
    const float* W4  = (const float*)d_in[13];
    const float* b4  = (const float*)d_in[14];
    const float* Wc  = (const float*)d_in[15];
    const float* bc  = (const float*)d_in[16];
    const float* init_emb = (const float*)d_in[17];
    float* out = (float*)d_out;

    const int vae_smem  = VAE_SMEM_FLOATS  * (int)sizeof(float);
    const int scan_smem = SCAN_SMEM_FLOATS * (int)sizeof(float);
    cudaFuncSetAttribute(vae_kernel,  cudaFuncAttributeMaxDynamicSharedMemorySize, vae_smem);
    cudaFuncSetAttribute(scan_kernel, cudaFuncAttributeMaxDynamicSharedMemorySize, scan_smem);

    vae_kernel<<<MTOT / 128, 256, vae_smem>>>(roles, eps, W1, b1, W21, b21,
                                              W22, b22, W3, b3, W4, b4);
    scan_kernel<<<Bc * CL, STH, scan_smem>>>(contexts, rand_vals, Wc, bc,
                                             init_emb, out);
}

// round 15
// speedup vs baseline: 1.0425x; 1.0425x over previous
#include <cuda_runtime.h>
#include <math.h>
#include <stdint.h>

// ---------------- problem constants ----------------
#define Bc   32
#define NRc  4096
#define DIN  384
#define DCTX 128
#define Hc   64
#define Ac   16
#define MTOT (Bc * NRc)

#define LOG_VAR2_C  (-4.6051701859880914f)
#define INV_VAR2_C  (100.0f)
#define STD2_C      (0.1f)

// ---------------- device scratch (zero-init at module load; scan re-zeros
// g_mse/g_kld at end of every launch so each launch starts from zeros) ----------
__device__ float g_embT[(size_t)Bc * Hc * NRc];   // [b][k][n]
__device__ float g_mse[Bc];
__device__ float g_kld[Bc];

// ---------------- tf32 helpers ----------------
__device__ __forceinline__ float tf32r(float x) {
    uint32_t u; asm("cvt.rna.tf32.f32 %0, %1;" : "=r"(u) : "f"(x));
    return __uint_as_float(u);
}
__device__ __forceinline__ void mma_tf32(float c[4], const uint32_t a[4],
                                         uint32_t b0, uint32_t b1) {
    asm volatile("mma.sync.aligned.m16n8k8.row.col.f32.tf32.tf32.f32 "
        "{%0,%1,%2,%3}, {%4,%5,%6,%7}, {%8,%9}, {%0,%1,%2,%3};"
        : "+f"(c[0]), "+f"(c[1]), "+f"(c[2]), "+f"(c[3])
        : "r"(a[0]), "r"(a[1]), "r"(a[2]), "r"(a[3]), "r"(b0), "r"(b1));
}

#define WSP 68   // conflict-free row stride (floats)

// ---------------- fused VAE kernel ----------------
// + merged W22/W21 dual-accumulator GEMM (shared Hs operand reads)
#define VAE_SMEM_FLOATS (2048 + 1024 + 8320 + 64*WSP + 4096 + 64 + 128)

__global__ __launch_bounds__(256, 2)
void vae_kernel(const float* __restrict__ roles, const float* __restrict__ eps,
                const float* __restrict__ W1,  const float* __restrict__ b1,
                const float* __restrict__ W21, const float* __restrict__ b21,
                const float* __restrict__ W22, const float* __restrict__ b22,
                const float* __restrict__ W3,  const float* __restrict__ b3,
                const float* __restrict__ W4,  const float* __restrict__ b4)
{
    extern __shared__ float sm[];
    float* As  = sm;                 // 16*128
    float* Bs  = As + 2048;          // 16*64
    float* Hs  = Bs + 1024;          // 128*65
    float* Ws  = Hs + 8320;          // 64*WSP  (W22 plain / W3,W4 permuted)
    float* Ws2 = Ws + 64*WSP;        // 64*64   (W21 plain)
    float* red = Ws2 + 4096;         // 64
    float* rns = red + 64;           // 128

    const int tid  = threadIdx.x;
    const int tcol = tid & 15;
    const int trow = tid >> 4;
    const int row0 = blockIdx.x * 128;
    const int b    = row0 >> 12;

    float acc[8][4];

    // ================= GEMM1: h = relu(roles @ W1 + b1)  [fp32, prefetched] =====
#pragma unroll
    for (int i = 0; i < 8; i++)
#pragma unroll
        for (int j = 0; j < 4; j++) acc[i][j] = 0.0f;

    const int am0 = tid >> 2;
    const int ak0 = (tid & 3) * 4;
    const int am1 = (tid + 256) >> 2;
    const int ak1 = ((tid + 256) & 3) * 4;
    const int bk  = tid >> 4;
    const int bj4 = (tid & 15) * 4;

    float4 va0, va1, vb;
    va0 = *reinterpret_cast<const float4*>(roles + (size_t)(row0 + am0) * DIN + ak0);
    va1 = *reinterpret_cast<const float4*>(roles + (size_t)(row0 + am1) * DIN + ak1);
    vb  = *reinterpret_cast<const float4*>(W1 + (size_t)bk * Hc + bj4);

    for (int t = 0; t < 24; t++) {
        As[(ak0 + 0) * 128 + am0] = va0.x;
        As[(ak0 + 1) * 128 + am0] = va0.y;
        As[(ak0 + 2) * 128 + am0] = va0.z;
        As[(ak0 + 3) * 128 + am0] = va0.w;
        As[(ak1 + 0) * 128 + am1] = va1.x;
        As[(ak1 + 1) * 128 + am1] = va1.y;
        As[(ak1 + 2) * 128 + am1] = va1.z;
        As[(ak1 + 3) * 128 + am1] = va1.w;
        *reinterpret_cast<float4*>(&Bs[bk * 64 + bj4]) = vb;
        __syncthreads();

        if (t + 1 < 24) {
            const int kt = (t + 1) * 16;
            va0 = *reinterpret_cast<const float4*>(
                roles + (size_t)(row0 + am0) * DIN + kt + ak0);
            va1 = *reinterpret_cast<const float4*>(
                roles + (size_t)(row0 + am1) * DIN + kt + ak1);
            vb  = *reinterpret_cast<const float4*>(
                W1 + (size_t)(kt + bk) * Hc + bj4);
        }

#pragma unroll
        for (int k = 0; k < 16; k++) {
            float a[8];
            *reinterpret_cast<float4*>(&a[0]) = *reinterpret_cast<float4*>(&As[k*128 + trow*8]);
            *reinterpret_cast<float4*>(&a[4]) = *reinterpret_cast<float4*>(&As[k*128 + trow*8 + 4]);
            float4 bb = *reinterpret_cast<float4*>(&Bs[k*64 + tcol*4]);
#pragma unroll
            for (int i = 0; i < 8; i++) {
                acc[i][0] += a[i] * bb.x;
                acc[i][1] += a[i] * bb.y;
                acc[i][2] += a[i] * bb.z;
                acc[i][3] += a[i] * bb.w;
            }
        }
        __syncthreads();
    }
    {
        float4 bv = *reinterpret_cast<const float4*>(b1 + tcol * 4);
#pragma unroll
        for (int i = 0; i < 8; i++) {
            int r = trow * 8 + i;
            Hs[r*65 + tcol*4 + 0] = fmaxf(acc[i][0] + bv.x, 0.0f);
            Hs[r*65 + tcol*4 + 1] = fmaxf(acc[i][1] + bv.y, 0.0f);
            Hs[r*65 + tcol*4 + 2] = fmaxf(acc[i][2] + bv.z, 0.0f);
            Hs[r*65 + tcol*4 + 3] = fmaxf(acc[i][3] + bv.w, 0.0f);
        }
    }
    // stage BOTH W22 (Ws, plain) and W21 (Ws2, plain)
    for (int t = tid; t < 1024; t += 256) {
        *reinterpret_cast<float4*>(&Ws [t*4]) = *reinterpret_cast<const float4*>(W22 + t*4);
        *reinterpret_cast<float4*>(&Ws2[t*4]) = *reinterpret_cast<const float4*>(W21 + t*4);
    }
    __syncthreads();

    float kacc = 0.0f;

    // ========== MERGED: log_var = h@W22+b22  AND  mu = h@W21+b21  [fp32] ========
    float ac2[8][4];   // log_var accumulators
#pragma unroll
    for (int i = 0; i < 8; i++)
#pragma unroll
        for (int j = 0; j < 4; j++) { acc[i][j] = 0.0f; ac2[i][j] = 0.0f; }
#pragma unroll 4
    for (int k = 0; k < 64; k++) {
        float a[8];
#pragma unroll
        for (int i = 0; i < 8; i++) a[i] = Hs[(trow*8 + i)*65 + k];
        float4 b2 = *reinterpret_cast<float4*>(&Ws [k*64 + tcol*4]);
        float4 b1v = *reinterpret_cast<float4*>(&Ws2[k*64 + tcol*4]);
#pragma unroll
        for (int i = 0; i < 8; i++) {
            ac2[i][0] += a[i]*b2.x;  ac2[i][1] += a[i]*b2.y;
            ac2[i][2] += a[i]*b2.z;  ac2[i][3] += a[i]*b2.w;
            acc[i][0] += a[i]*b1v.x; acc[i][1] += a[i]*b1v.y;
            acc[i][2] += a[i]*b1v.z; acc[i][3] += a[i]*b1v.w;
        }
    }
    // fused epilogue: kld terms + z = mu + eps * exp(0.5 lv) * STD2
    {
        float4 bv22 = *reinterpret_cast<const float4*>(b22 + tcol * 4);
        float4 bv21 = *reinterpret_cast<const float4*>(b21 + tcol * 4);
        float b22a[4] = {bv22.x, bv22.y, bv22.z, bv22.w};
        float b21a[4] = {bv21.x, bv21.y, bv21.z, bv21.w};
#pragma unroll
        for (int i = 0; i < 8; i++) {
            float4 ev = *reinterpret_cast<const float4*>(
                eps + (size_t)(row0 + trow*8 + i) * Hc + tcol * 4);
            float eva[4] = {ev.x, ev.y, ev.z, ev.w};
#pragma unroll
            for (int j = 0; j < 4; j++) {
                float lv = ac2[i][j] + b22a[j];
                float ex = expf(lv);
                kacc += (1.0f - LOG_VAR2_C + lv - ex * INV_VAR2_C);
                float mu = acc[i][j] + b21a[j];
                kacc -= mu * mu * INV_VAR2_C;
                float s  = expf(0.5f * lv) * STD2_C;
                acc[i][j] = mu + eva[j] * s;    // z
            }
        }
    }
    __syncthreads();
    // z (fp32) -> Hs ; stage Ws = permuted tf32(W3)
#pragma unroll
    for (int i = 0; i < 8; i++) {
        int r = trow * 8 + i;
        Hs[r*65 + tcol*4 + 0] = acc[i][0];
        Hs[r*65 + tcol*4 + 1] = acc[i][1];
        Hs[r*65 + tcol*4 + 2] = acc[i][2];
        Hs[r*65 + tcol*4 + 3] = acc[i][3];
    }
    for (int t = tid; t < 4096; t += 256) {
        int k = t >> 6, n = t & 63;
        Ws[k*WSP + ((n & 7) << 3) + (n >> 3)] = tf32r(W3[t]);
    }
    __syncthreads();

    // ================= role_emb = l2norm(z), stored transposed =================
    if (tid < 128) {
        float ss = 0.0f;
#pragma unroll
        for (int k = 0; k < 64; k++) { float v = Hs[tid*65 + k]; ss += v * v; }
        rns[tid] = 1.0f / fmaxf(sqrtf(ss), 1e-12f);
    }
    __syncthreads();
    {
        const int nloc0 = row0 & (NRc - 1);
        for (int t = tid; t < 128 * 64; t += 256) {
            int k = t >> 7;
            int r = t & 127;
            g_embT[((size_t)b * Hc + k) * NRc + nloc0 + r] = Hs[r*65 + k] * rns[r];
        }
    }
    // z rounding happens in fragment build below (no smem pass)

    // ================= tf32 HMMA path: g = relu(z@W3+b3); mse(g@W4+b4) ========
    const int wid  = tid >> 5;
    const int lane = tid & 31;
    const int gid  = lane >> 2;
    const int tig  = lane & 3;
    const int mrow = wid * 16;

    uint32_t afr[8][4];
#pragma unroll
    for (int kt = 0; kt < 8; kt++) {
        int k0 = kt * 8;
        afr[kt][0] = __float_as_uint(tf32r(Hs[(mrow+gid  )*65 + k0+tig  ]));
        afr[kt][1] = __float_as_uint(tf32r(Hs[(mrow+gid+8)*65 + k0+tig  ]));
        afr[kt][2] = __float_as_uint(tf32r(Hs[(mrow+gid  )*65 + k0+tig+4]));
        afr[kt][3] = __float_as_uint(tf32r(Hs[(mrow+gid+8)*65 + k0+tig+4]));
    }
    float cfr[8][4];
#pragma unroll
    for (int nt = 0; nt < 8; nt++)
#pragma unroll
        for (int j = 0; j < 4; j++) cfr[nt][j] = 0.0f;
#pragma unroll
    for (int kt = 0; kt < 8; kt++) {
        const float4* p0 = reinterpret_cast<const float4*>(&Ws[(kt*8+tig  )*WSP + gid*8]);
        const float4* p1 = reinterpret_cast<const float4*>(&Ws[(kt*8+tig+4)*WSP + gid*8]);
        float4 b0a = p0[0], b0b = p0[1];
        float4 b1a = p1[0], b1b = p1[1];
        mma_tf32(cfr[0], afr[kt], __float_as_uint(b0a.x), __float_as_uint(b1a.x));
        mma_tf32(cfr[1], afr[kt], __float_as_uint(b0a.y), __float_as_uint(b1a.y));
        mma_tf32(cfr[2], afr[kt], __float_as_uint(b0a.z), __float_as_uint(b1a.z));
        mma_tf32(cfr[3], afr[kt], __float_as_uint(b0a.w), __float_as_uint(b1a.w));
        mma_tf32(cfr[4], afr[kt], __float_as_uint(b0b.x), __float_as_uint(b1b.x));
        mma_tf32(cfr[5], afr[kt], __float_as_uint(b0b.y), __float_as_uint(b1b.y));
        mma_tf32(cfr[6], afr[kt], __float_as_uint(b0b.z), __float_as_uint(b1b.z));
        mma_tf32(cfr[7], afr[kt], __float_as_uint(b0b.w), __float_as_uint(b1b.w));
    }
    __syncthreads();
#pragma unroll
    for (int nt = 0; nt < 8; nt++) {
        int col = nt*8 + 2*tig;
        float2 b3v = *reinterpret_cast<const float2*>(b3 + col);
        Hs[(mrow+gid  )*65 + col    ] = tf32r(fmaxf(cfr[nt][0] + b3v.x, 0.0f));
        Hs[(mrow+gid  )*65 + col + 1] = tf32r(fmaxf(cfr[nt][1] + b3v.y, 0.0f));
        Hs[(mrow+gid+8)*65 + col    ] = tf32r(fmaxf(cfr[nt][2] + b3v.x, 0.0f));
        Hs[(mrow+gid+8)*65 + col + 1] = tf32r(fmaxf(cfr[nt][3] + b3v.y, 0.0f));
    }
    __syncthreads();
#pragma unroll
    for (int kt = 0; kt < 8; kt++) {
        int k0 = kt * 8;
        afr[kt][0] = __float_as_uint(Hs[(mrow+gid  )*65 + k0+tig  ]);
        afr[kt][1] = __float_as_uint(Hs[(mrow+gid+8)*65 + k0+tig  ]);
        afr[kt][2] = __float_as_uint(Hs[(mrow+gid  )*65 + k0+tig+4]);
        afr[kt][3] = __float_as_uint(Hs[(mrow+gid+8)*65 + k0+tig+4]);
    }

    // W4 chunk staging: thread owns 16 consecutive floats; double-buffered
    const int sk = tid >> 2;
    const int sn = (tid & 3) * 16;
    float4 wpre[4];
#pragma unroll
    for (int q = 0; q < 4; q++)
        wpre[q] = *reinterpret_cast<const float4*>(
            W4 + (size_t)sk * DIN + sn + q * 4);

    float msacc = 0.0f;
    for (int ch = 0; ch < 6; ch++) {
        __syncthreads();
        {
            const float* wf = reinterpret_cast<const float*>(wpre);
#pragma unroll
            for (int j = 0; j < 16; j++) {
                int n = sn + j;
                Ws[sk*WSP + ((n & 7) << 3) + (n >> 3)] = tf32r(wf[j]);
            }
        }
        __syncthreads();
        if (ch + 1 < 6) {
#pragma unroll
            for (int q = 0; q < 4; q++)
                wpre[q] = *reinterpret_cast<const float4*>(
                    W4 + (size_t)sk * DIN + (ch + 1) * 64 + sn + q * 4);
        }
        float cf[8][4];
#pragma unroll
        for (int nt = 0; nt < 8; nt++)
#pragma unroll
            for (int j = 0; j < 4; j++) cf[nt][j] = 0.0f;
#pragma unroll
        for (int kt = 0; kt < 8; kt++) {
            const float4* p0 = reinterpret_cast<const float4*>(&Ws[(kt*8+tig  )*WSP + gid*8]);
            const float4* p1 = reinterpret_cast<const float4*>(&Ws[(kt*8+tig+4)*WSP + gid*8]);
            float4 b0a = p0[0], b0b = p0[1];
            float4 b1a = p1[0], b1b = p1[1];
            mma_tf32(cf[0], afr[kt], __float_as_uint(b0a.x), __float_as_uint(b1a.x));
            mma_tf32(cf[1], afr[kt], __float_as_uint(b0a.y), __float_as_uint(b1a.y));
            mma_tf32(cf[2], afr[kt], __float_as_uint(b0a.z), __float_as_uint(b1a.z));
            mma_tf32(cf[3], afr[kt], __float_as_uint(b0a.w), __float_as_uint(b1a.w));
            mma_tf32(cf[4], afr[kt], __float_as_uint(b0b.x), __float_as_uint(b1b.x));
            mma_tf32(cf[5], afr[kt], __float_as_uint(b0b.y), __float_as_uint(b1b.y));
            mma_tf32(cf[6], afr[kt], __float_as_uint(b0b.z), __float_as_uint(b1b.z));
            mma_tf32(cf[7], afr[kt], __float_as_uint(b0b.w), __float_as_uint(b1b.w));
        }
#pragma unroll
        for (int nt = 0; nt < 8; nt++) {
            int col = ch*64 + nt*8 + 2*tig;
            float2 b4v = *reinterpret_cast<const float2*>(b4 + col);
            float2 r0v = *reinterpret_cast<const float2*>(
                roles + (size_t)(row0 + mrow + gid    ) * DIN + col);
            float2 r1v = *reinterpret_cast<const float2*>(
                roles + (size_t)(row0 + mrow + gid + 8) * DIN + col);
            float d;
            d = cf[nt][0] + b4v.x - r0v.x; msacc += d*d;
            d = cf[nt][1] + b4v.y - r0v.y; msacc += d*d;
            d = cf[nt][2] + b4v.x - r1v.x; msacc += d*d;
            d = cf[nt][3] + b4v.y - r1v.y; msacc += d*d;
        }
    }

    // ================= block reduce kld / mse =================
    float ks = kacc, ms = msacc;
#pragma unroll
    for (int off = 16; off > 0; off >>= 1) {
        ks += __shfl_xor_sync(0xffffffffu, ks, off);
        ms += __shfl_xor_sync(0xffffffffu, ms, off);
    }
    __syncthreads();
    if ((tid & 31) == 0) { red[tid >> 5] = ks; red[8 + (tid >> 5)] = ms; }
    __syncthreads();
    if (tid == 0) {
        float kt = 0.0f, mt = 0.0f;
#pragma unroll
        for (int w = 0; w < 8; w++) { kt += red[w]; mt += red[8 + w]; }
        atomicAdd(&g_kld[b], kt);
        atomicAdd(&g_mse[b], mt);
    }
}

// ---------------- cluster / mbarrier helpers ----------------
__device__ __forceinline__ uint32_t s2u(const void* p) {
    uint32_t a;
    asm("{ .reg .u64 t; cvta.to.shared.u64 t, %1; cvt.u32.u64 %0, t; }" : "=r"(a) : "l"(p));
    return a;
}
__device__ __forceinline__ void mbar_init(uint32_t mbar, uint32_t cnt) {
    asm volatile("mbarrier.init.shared.b64 [%0], %1;" :: "r"(mbar), "r"(cnt) : "memory");
}
__device__ __forceinline__ void mbar_expect_tx(uint32_t mbar, uint32_t bytes) {
    asm volatile("mbarrier.arrive.expect_tx.shared.b64 _, [%0], %1;"
                 :: "r"(mbar), "r"(bytes) : "memory");
}
__device__ __forceinline__ void st_async_b32(uint32_t slot, uint32_t mbar,
                                             uint32_t peer, uint32_t val) {
    uint32_t rs, rb;
    asm("mapa.shared::cluster.u32 %0, %1, %2;" : "=r"(rs) : "r"(slot), "r"(peer));
    asm("mapa.shared::cluster.u32 %0, %1, %2;" : "=r"(rb) : "r"(mbar), "r"(peer));
    asm volatile("st.async.shared::cluster.mbarrier::complete_tx::bytes.b32 [%0], %1, [%2];"
                 :: "r"(rs), "r"(val), "r"(rb) : "memory");
}
__device__ __forceinline__ void mbar_wait_cluster(uint32_t mbar, uint32_t parity) {
    uint32_t done;
    asm volatile("{\n\t.reg .pred p;\n\t"
        "mbarrier.try_wait.parity.acquire.cluster.shared::cta.b64 p, [%1], %2;\n\t"
        "selp.b32 %0, 1, 0, p;\n\t}"
        : "=r"(done) : "r"(mbar), "r"(parity) : "memory");
    while (!done) {
        asm volatile("{\n\t.reg .pred p;\n\t"
            "mbarrier.try_wait.parity.acquire.cluster.shared::cta.b64 p, [%1], %2, 0x989680;\n\t"
            "selp.b32 %0, 1, 0, p;\n\t}"
            : "=r"(done) : "r"(mbar), "r"(parity) : "memory");
    }
}
#define CLUSTER_SYNC() do { \
    asm volatile("barrier.cluster.arrive.aligned;" ::: "memory"); \
    asm volatile("barrier.cluster.wait.aligned;"   ::: "memory"); } while (0)

// ---------------- cluster-parallel selection scan (frozen) ----------
#define CL 4
#define STH 512
#define RPC (NRc / CL)
#define NCACHE 768
#define SCAN_SMEM_FLOATS (1024 + 64*NCACHE)

__global__ __launch_bounds__(STH, 1) __cluster_dims__(CL, 1, 1)
void scan_kernel(const float* __restrict__ contexts, const float* __restrict__ rand_vals,
                 const float* __restrict__ Wc, const float* __restrict__ bc,
                 const float* __restrict__ init_emb, float* __restrict__ out)
{
    extern __shared__ float sm[];
    unsigned long long* mbar = (unsigned long long*)sm;
    float* exchS = sm + 4;
    int*   exchC = (int*)(sm + 12);
    int*   seli  = (int*)(sm + 20);
    float* scal  = sm + 21;
    float* wred  = sm + 28;
    float* wexc  = sm + 44;
    float* ctxs  = sm + 60;
    float* bcs   = sm + 188;
    float* hist  = sm + 252;
    float* cur   = sm + 316;
    float* tmp   = sm + 380;
    float* cvec  = sm + 444;
    float* cpart = sm + 508;
    float* embc  = sm + 1024;

    const int b    = blockIdx.x >> 2;
    const int rank = blockIdx.x & 3;
    const int tid  = threadIdx.x;
    const int lane = tid & 31;
    const int wid  = tid >> 5;

    if (blockIdx.x == 0 && tid == 0) {
        float v = 0.0f;
        for (int bb = 0; bb < Bc; bb++) {
            float mse = g_mse[bb] * (1.0f / ((float)NRc * (float)DIN));
            float kld = (-0.5f / ((float)NRc * (float)Hc)) * g_kld[bb];
            v += mse + kld;
        }
        out[Bc*Ac + Bc + Bc*Hc] = v / (float)Bc;
        for (int bb = 0; bb < Bc; bb++) { g_mse[bb] = 0.0f; g_kld[bb] = 0.0f; }
    }

    const uint32_t mbarS_a = s2u(&mbar[0]);
    const uint32_t mbarC_a = s2u(&mbar[1]);

    const float* embT = g_embT + (size_t)b * Hc * NRc;

    const int col  = tid & 63;
    const int irow = (tid >> 6) * 24;
    float wreg[24];
#pragma unroll
    for (int i = 0; i < 24; i++) wreg[i] = Wc[(size_t)(irow + i) * 64 + col];

    for (int t = tid; t < 64 * NCACHE / 4; t += STH) {
        int k  = t / (NCACHE / 4);
        int n4 = (t % (NCACHE / 4)) * 4;
        *reinterpret_cast<float4*>(&embc[k * NCACHE + n4]) =
            *reinterpret_cast<const float4*>(embT + (size_t)k * NRc + rank * RPC + n4);
    }
    if (tid < 128) ctxs[tid] = contexts[b * DCTX + tid];
    if (tid < 64)  { bcs[tid] = bc[tid]; float iv = init_emb[tid]; hist[tid] = iv; cur[tid] = iv; }
    if (tid == 0)  {
        scal[0] = 0.0f;
        mbar_init(mbarS_a, 1);
        mbar_init(mbarC_a, 1);
    }
    __syncthreads();
    CLUSTER_SYNC();

    for (int step = 0; step < Ac; step++) {
        const uint32_t par = (uint32_t)(step & 1);
        const uint32_t slotS = s2u(&exchS[(step & 1) * 4 + rank]);
        const uint32_t slotC = s2u(&exchC[(step & 1) * 4 + rank]);

        if (tid == 0) {
            mbar_expect_tx(mbarS_a, 16);
            mbar_expect_tx(mbarC_a, 16);
            seli[0] = 0x7fffffff;
        }
        if (tid < 64) tmp[tid] = hist[tid] + cur[tid];
        __syncthreads();
        if (wid == 0) {
            float x0 = tmp[lane], x1 = tmp[lane + 32];
            float s = x0 + x1;
#pragma unroll
            for (int off = 16; off > 0; off >>= 1) s += __shfl_xor_sync(0xffffffffu, s, off);
            float mean = s * (1.0f / 64.0f);
            float d0 = x0 - mean, d1 = x1 - mean;
            float vs = d0*d0 + d1*d1;
#pragma unroll
            for (int off = 16; off > 0; off >>= 1) vs += __shfl_xor_sync(0xffffffffu, vs, off);
            if (lane == 0) {
                scal[1] = mean;
                scal[2] = 1.0f / sqrtf(vs * (1.0f / 64.0f) + 1e-5f);
            }
        }
        __syncthreads();
        if (tid < 64) hist[tid] = (tmp[tid] - scal[1]) * scal[2];
        __syncthreads();

        {
            float s = 0.0f;
#pragma unroll
            for (int i = 0; i < 24; i++) {
                int gi = irow + i;
                float x = (gi < 128) ? ctxs[gi] : hist[gi - 128];
                s = fmaf(x, wreg[i], s);
            }
            cpart[(tid >> 6) * 64 + col] = s;
        }
        __syncthreads();
        if (tid < 64) {
            float s = bcs[tid];
#pragma unroll
            for (int p = 0; p < 8; p++) s += cpart[p*64 + tid];
            cvec[tid] = s;
        }
        __syncthreads();

        float invc;
        {
            float c0 = cvec[lane], c1 = cvec[lane + 32];
            float ssn = c0*c0 + c1*c1;
#pragma unroll
            for (int off = 16; off > 0; off >>= 1)
                ssn += __shfl_xor_sync(0xffffffffu, ssn, off);
            invc = 1.0f / fmaxf(sqrtf(ssn), 1e-12f);
        }

        float sx = 0.f, sy = 0.f;
        if (tid < NCACHE / 2) {
            const float* ep = embc + 2 * tid;
#pragma unroll 8
            for (int k = 0; k < 64; k++) {
                float2 v = *reinterpret_cast<const float2*>(ep + k * NCACHE);
                float ck = cvec[k];
                sx = fmaf(v.x, ck, sx); sy = fmaf(v.y, ck, sy);
            }
        } else {
            const float* ep = embT + rank * RPC + 2 * tid;
#pragma unroll 16
            for (int k = 0; k < 64; k++) {
                float2 v = *reinterpret_cast<const float2*>(ep + (size_t)k * NRc);
                float ck = cvec[k];
                sx = fmaf(v.x, ck, sx); sy = fmaf(v.y, ck, sy);
            }
        }
        float e0 = expf(sx * invc), e1 = expf(sy * invc);
        float t2 = e0 + e1;

        float incl = t2;
#pragma unroll
        for (int off = 1; off < 32; off <<= 1) {
            float n = __shfl_up_sync(0xffffffffu, incl, off);
            if (lane >= off) incl += n;
        }
        if (lane == 31) wred[wid] = incl;
        __syncthreads();
        if (tid == 0) {
            float s = 0.0f;
#pragma unroll
            for (int w = 0; w < 16; w++) { float v = wred[w]; wexc[w] = s; s += v; }
            scal[4] = s;
        }
        __syncthreads();
        float S_local  = scal[4];
        float excl_thr = wexc[wid] + (incl - t2);

        if (tid < CL) st_async_b32(slotS, mbarS_a, (uint32_t)tid, __float_as_uint(S_local));
        mbar_wait_cluster(mbarS_a, par);
        float S_tot = 0.0f, pre = 0.0f;
#pragma unroll
        for (int r = 0; r < CL; r++) {
            float v = exchS[(step & 1) * 4 + r];
            if (r < rank) pre += v;
            S_tot += v;
        }

        float T = rand_vals[b * Ac + step] * S_tot;
        float base = pre + excl_thr;
        int cand = 0x7fffffff;
        int gr = rank * RPC + tid * 2;
        if      (base + e0 > T) cand = gr;
        else if (base + t2 > T) cand = gr + 1;
        if (cand != 0x7fffffff) atomicMin(seli, cand);
        __syncthreads();
        int lc = seli[0];
        if (tid < CL) st_async_b32(slotC, mbarC_a, (uint32_t)tid, (uint32_t)lc);
        mbar_wait_cluster(mbarC_a, par);
        int sel = 0x7fffffff;
#pragma unroll
        for (int r = 0; r < CL; r++) sel = min(sel, exchC[(step & 1) * 4 + r]);
        if (sel == 0x7fffffff) sel = 0;

        if (tid < 64) cur[tid] = embT[(size_t)tid * NRc + sel];
        __syncthreads();
        if (wid == 0) {
            float d = cur[lane] * cvec[lane] + cur[lane + 32] * cvec[lane + 32];
#pragma unroll
            for (int off = 16; off > 0; off >>= 1) d += __shfl_xor_sync(0xffffffffu, d, off);
            if (lane == 0) scal[0] += d * invc - logf(S_tot);
        }
        if (rank == 0 && tid == 0) out[b * Ac + step] = (float)sel;
        __syncthreads();
    }

    if (rank == 0 && tid == 0) out[Bc*Ac + b] = scal[0];
    if (rank == 0 && tid < 64) out[Bc*Ac + Bc + b*Hc + tid] = hist[tid];
    CLUSTER_SYNC();
}

// ---------------- launcher ----------------
extern "C" void kernel_launch(void* const* d_in, const int* in_sizes, int n_in,
                              void* d_out, int out_size) {
    const float* roles     = (const float*)d_in[0];
    const float* contexts  = (const float*)d_in[1];
    const float* eps       = (const float*)d_in[2];
    const float* rand_vals = (const float*)d_in[3];
    const float* W1  = (const float*)d_in[5];
    const float* b1  = (const float*)d_in[6];
    const float* W21 = (const float*)d_in[7];
    const float* b21 = (const float*)d_in[8];
    const float* W22 = (const float*)d_in[9];
    const float* b22 = (const float*)d_in[10];
    const float* W3  = (const float*)d_in[11];
    const float* b3  = (const float*)d_in[12];
    const float* W4  = (const float*)d_in[13];
    const float* b4  = (const float*)d_in[14];
    const float* Wc  = (const float*)d_in[15];
    const float* bc  = (const float*)d_in[16];
    const float* init_emb = (const float*)d_in[17];
    float* out = (float*)d_out;

    const int vae_smem  = VAE_SMEM_FLOATS  * (int)sizeof(float);
    const int scan_smem = SCAN_SMEM_FLOATS * (int)sizeof(float);
    cudaFuncSetAttribute(vae_kernel,  cudaFuncAttributeMaxDynamicSharedMemorySize, vae_smem);
    cudaFuncSetAttribute(scan_kernel, cudaFuncAttributeMaxDynamicSharedMemorySize, scan_smem);

    vae_kernel<<<MTOT / 128, 256, vae_smem>>>(roles, eps, W1, b1, W21, b21,
                                              W22, b22, W3, b3, W4, b4);
    scan_kernel<<<Bc * CL, STH, scan_smem>>>(contexts, rand_vals, Wc, bc,
                                             init_emb, out);
}